// round 13
// baseline (speedup 1.0000x reference)
#include <cuda_runtime.h>
#include <cstdint>

#define DEVI __device__ __forceinline__

// Problem constants
static constexpr int B_TOT  = 16384;
static constexpr int F_DIM  = 50;
static constexpr int E_DIM  = 64;
static constexpr int D_DIM  = 128;
static constexpr int FE     = F_DIM * E_DIM;      // 3200 floats per batch

// Kernel config: 3 CTAs/SM, 256 threads (8 warps), 2 batches per CTA-iteration
static constexpr int NTHREADS = 256;
static constexpr int GRID     = 456;              // 3 CTAs per SM on GB300
static constexpr int BPI      = 2;
static constexpr int NGI      = B_TOT / BPI;      // 8192 groups
static constexpr int GRP_G    = BPI * FE;         // GMEM group stride (6400 floats)

// fp32 staging: [buf(2)][batch(2)][f(50) rows, stride 68]
static constexpr int ST_STR   = 68;               // conflict-free for B-frag reads
static constexpr int ST_BATCH = F_DIM * ST_STR;   // 3400 floats
static constexpr int ST_GRP   = BPI * ST_BATCH;   // 6800 floats per SMEM buffer

// A-frag table: [mq(4)][s(4)][mi(2)][lane(32)][reg(4)] u32 (f16x2, frag order)
static constexpr int AFRAG_U32 = 4 * 4 * 2 * 32 * 4;          // 4096 (16 KB)

// SMEM map (u32)
static constexpr int ST_OFF    = AFRAG_U32;                    // 4096
static constexpr int SMEM_U32  = ST_OFF + 2 * ST_GRP;          // 17696
static constexpr int SMEM_BYTES = SMEM_U32 * 4;                // 70784 B -> 3 CTAs/SM

// Pairs per group for the owned prefetch: b(2) x f2(25) x seg(16)
static constexpr int NPAIRS = BPI * 25 * 16;                   // 800

// ---------------------------------------------------------------------------
DEVI uint32_t smem_u32(const void* p) {
    uint32_t a;
    asm("{ .reg .u64 t; cvta.to.shared.u64 t, %1; cvt.u32.u64 %0, t; }" : "=r"(a) : "l"(p));
    return a;
}
DEVI uint32_t pack_h2(float lo, float hi) {
    uint32_t r;
    asm("cvt.rn.f16x2.f32 %0, %1, %2;" : "=r"(r) : "f"(hi), "f"(lo));
    return r;
}
DEVI void mma16n8k16(float& c0, float& c1, float& c2, float& c3,
                     uint32_t a0, uint32_t a1, uint32_t a2, uint32_t a3,
                     uint32_t b0, uint32_t b1) {
    asm volatile(
        "mma.sync.aligned.m16n8k16.row.col.f32.f16.f16.f32 "
        "{%0,%1,%2,%3}, {%4,%5,%6,%7}, {%8,%9}, {%0,%1,%2,%3};"
        : "+f"(c0), "+f"(c1), "+f"(c2), "+f"(c3)
        : "r"(a0), "r"(a1), "r"(a2), "r"(a3), "r"(b0), "r"(b1));
}
DEVI void cp_async16(uint32_t dst, const void* src) {
    asm volatile("cp.async.cg.shared.global [%0], [%1], 16;" :: "r"(dst), "l"(src) : "memory");
}
DEVI void cp_commit()  { asm volatile("cp.async.commit_group;" ::: "memory"); }
DEVI void cp_wait1()   { asm volatile("cp.async.wait_group 1;" ::: "memory"); }

// Prefetch one group (2 batches) into stage[buf]: per pair, rows 2f2 and 2f2+1
DEVI void prefetch(uint32_t stage_addr, const float* __restrict__ gb, int buf, int tid) {
    const uint32_t dbase = stage_addr + (uint32_t)(buf * ST_GRP) * 4u;
#pragma unroll 1
    for (int p = tid; p < NPAIRS; p += NTHREADS) {
        int b   = p / 400;
        int r   = p - b * 400;
        int f2  = r >> 4;
        int seg = r & 15;
        const float* src = gb + b * FE + (2 * f2) * E_DIM + seg * 4;
        uint32_t dst = dbase + (uint32_t)(b * ST_BATCH + (2 * f2) * ST_STR + seg * 4) * 4u;
        cp_async16(dst, src);
        cp_async16(dst + ST_STR * 4u, src + E_DIM);
    }
}

// ---------------------------------------------------------------------------
__global__ void __launch_bounds__(NTHREADS, 3)
InnerProduct_65429531787441_kernel(const float* __restrict__ X,
                                   const float* __restrict__ Th,
                                   float* __restrict__ out) {
    extern __shared__ uint32_t smu[];
    uint32_t* afr   = smu;                            // A-frag table (f16x2)
    float*    stage = reinterpret_cast<float*>(smu + ST_OFF);
    const uint32_t stage_addr = smem_u32(stage);

    const int tid  = threadIdx.x;
    const int lane = tid & 31;
    const int w    = tid >> 5;
    const int b_l  = w >> 2;        // batch slot 0..1
    const int mq   = w & 3;         // d quarter
    const int lg   = lane >> 2;     // 0..7
    const int lq   = lane & 3;      // 0..3

    const int gi0 = blockIdx.x;

    // Prologue: prefetch groups gi0 (buf 0) and gi0+GRID (buf 1)
    prefetch(stage_addr, X + (size_t)gi0 * GRP_G, 0, tid);
    cp_commit();
    if (gi0 + GRID < NGI)
        prefetch(stage_addr, X + (size_t)(gi0 + GRID) * GRP_G, 1, tid);
    cp_commit();

    // Build A-frag table (Theta fp16 pairs, m16n8k16 frag order, zero-pad f>=50)
    for (int i = tid; i < AFRAG_U32; i += NTHREADS) {
        int j   = i & 3;
        int ln  = (i >> 2) & 31;
        int mi  = (i >> 7) & 1;
        int s   = (i >> 8) & 3;
        int mq_ = i >> 10;
        int row = mq_ * 32 + mi * 16 + (j & 1) * 8 + (ln >> 2);
        int k0  = 16 * s + 2 * (ln & 3) + (j >> 1) * 8;
        float v0 = (k0     < F_DIM) ? Th[row * F_DIM + k0]     : 0.f;
        float v1 = (k0 + 1 < F_DIM) ? Th[row * F_DIM + k0 + 1] : 0.f;
        afr[i] = pack_h2(v0, v1);
    }

    cp_wait1();                     // group gi0 complete
    __syncthreads();                // publish afr + stage[0]

    const uint4* afr4 = reinterpret_cast<const uint4*>(afr);

    int it = 0;
    for (int gi = gi0; gi < NGI; gi += GRID, ++it) {
        const int buf = it & 1;
        const float* st = stage + buf * ST_GRP + b_l * ST_BATCH;

        float acc[2][8][4];
#pragma unroll
        for (int mi = 0; mi < 2; mi++)
#pragma unroll
            for (int ni = 0; ni < 8; ni++)
#pragma unroll
                for (int j = 0; j < 4; j++) acc[mi][ni][j] = 0.f;

#pragma unroll
        for (int s = 0; s < 4; s++) {
            const uint4 A0 = afr4[((mq * 4 + s) * 2 + 0) * 32 + lane];
            const uint4 A1 = afr4[((mq * 4 + s) * 2 + 1) * 32 + lane];
            const int k0 = 16 * s + 2 * lq;
#pragma unroll
            for (int ni = 0; ni < 8; ni++) {
                const int e = ni * 8 + lg;
                uint32_t b0, b1;
                if (s < 3) {
                    // k0, k0+1, k0+8, k0+9 all < 50: unpredicated
                    b0 = pack_h2(st[k0 * ST_STR + e],       st[(k0 + 1) * ST_STR + e]);
                    b1 = pack_h2(st[(k0 + 8) * ST_STR + e], st[(k0 + 9) * ST_STR + e]);
                } else {
                    // s == 3: only lq==0 touches real data (k = 48, 49); rest zero
                    b0 = (lq == 0)
                         ? pack_h2(st[48 * ST_STR + e], st[49 * ST_STR + e])
                         : 0u;
                    b1 = 0u;
                }
                mma16n8k16(acc[0][ni][0], acc[0][ni][1], acc[0][ni][2], acc[0][ni][3],
                           A0.x, A0.y, A0.z, A0.w, b0, b1);
                mma16n8k16(acc[1][ni][0], acc[1][ni][1], acc[1][ni][2], acc[1][ni][3],
                           A1.x, A1.y, A1.z, A1.w, b0, b1);
            }
        }

        __syncthreads();            // all warps done reading stage[buf]

        // Refill stage[buf] with group gi+2*GRID (lands well before next use)
        if (gi + 2 * GRID < NGI)
            prefetch(stage_addr, X + (size_t)(gi + 2 * GRID) * GRP_G, buf, tid);
        cp_commit();                // keep group accounting on tail iterations

        // Epilogue overlaps with the in-flight cp.async
        float* orow = out + (size_t)(gi * BPI + b_l) * D_DIM;
#pragma unroll
        for (int mi = 0; mi < 2; mi++) {
            float a = 0.f, b = 0.f;
#pragma unroll
            for (int ni = 0; ni < 8; ni++) {
                a = fmaf(acc[mi][ni][0], acc[mi][ni][0], a);
                a = fmaf(acc[mi][ni][1], acc[mi][ni][1], a);
                b = fmaf(acc[mi][ni][2], acc[mi][ni][2], b);
                b = fmaf(acc[mi][ni][3], acc[mi][ni][3], b);
            }
            a += __shfl_xor_sync(0xffffffffu, a, 1);
            a += __shfl_xor_sync(0xffffffffu, a, 2);
            b += __shfl_xor_sync(0xffffffffu, b, 1);
            b += __shfl_xor_sync(0xffffffffu, b, 2);
            if (lq == 0) {
                const int d = mq * 32 + mi * 16 + lg;
                orow[d]     = a;
                orow[d + 8] = b;
            }
        }

        cp_wait1();                 // group gi+GRID (stage[buf^1]) complete
        __syncthreads();            // publish stage[buf^1]
    }
}

extern "C" void kernel_launch(void* const* d_in, const int* in_sizes, int n_in,
                              void* d_out, int out_size) {
    (void)in_sizes; (void)n_in; (void)out_size;
    const float* X  = (const float*)d_in[0];
    const float* Th = (const float*)d_in[1];
    float* out = (float*)d_out;
    cudaFuncSetAttribute(InnerProduct_65429531787441_kernel,
                         cudaFuncAttributeMaxDynamicSharedMemorySize, SMEM_BYTES);
    InnerProduct_65429531787441_kernel<<<GRID, NTHREADS, SMEM_BYTES>>>(X, Th, out);
}

// round 14
// speedup vs baseline: 2.5560x; 2.5560x over previous
#include <cuda_runtime.h>
#include <cstdint>

#define DEVI __device__ __forceinline__

// Problem constants
static constexpr int B_TOT  = 16384;
static constexpr int F_DIM  = 50;
static constexpr int E_DIM  = 64;
static constexpr int D_DIM  = 128;
static constexpr int FE     = F_DIM * E_DIM;      // 3200 floats per batch

// Kernel config: 3 CTAs/SM, 256 threads (8 warps), 2 batches per CTA-iteration
static constexpr int NTHREADS = 256;
static constexpr int GRID     = 456;              // 3 CTAs per SM on GB300
static constexpr int BPI      = 2;
static constexpr int NGI      = B_TOT / BPI;      // 8192 groups
static constexpr int GRP_G    = BPI * FE;         // GMEM group stride (6400 floats)

// fp16 tile: [f2 rows 0..24][e 64] stride 72 (rows 25+ never read: s=3 predicated)
static constexpr int F2_REAL   = 25;
static constexpr int X16_STR   = 72;
static constexpr int X16_BATCH = F2_REAL * X16_STR;          // 1800 u32
static constexpr int X16_BUF   = BPI * X16_BATCH;            // 3600 u32

// A-frag table: [mq(4)][s(4)][mi(2)][lane(32)][reg(4)] u32 (f16x2, frag order)
static constexpr int AFRAG_U32 = 4 * 4 * 2 * 32 * 4;         // 4096 (16 KB)

// fp32 staging: SINGLE buffer, linear copy of one group (2 batches)
static constexpr int ST_GRP    = BPI * FE;                   // 6400 floats (25.6 KB)

// SMEM map (u32)
static constexpr int X16_OFF   = AFRAG_U32;                  // 4096
static constexpr int ST_OFF    = X16_OFF + 2 * X16_BUF;      // 11296
static constexpr int SMEM_U32  = ST_OFF + ST_GRP;            // 17696
static constexpr int SMEM_BYTES = SMEM_U32 * 4;              // 70784 B -> 3 CTAs/SM

// Pairs per group for the owned prefetch/convert chain: b(2) x f2(25) x seg(16)
static constexpr int NPAIRS = BPI * F2_REAL * 16;            // 800

// ---------------------------------------------------------------------------
DEVI uint32_t smem_u32(const void* p) {
    uint32_t a;
    asm("{ .reg .u64 t; cvta.to.shared.u64 t, %1; cvt.u32.u64 %0, t; }" : "=r"(a) : "l"(p));
    return a;
}
DEVI uint32_t pack_h2(float lo, float hi) {
    uint32_t r;
    asm("cvt.rn.f16x2.f32 %0, %1, %2;" : "=r"(r) : "f"(hi), "f"(lo));
    return r;
}
DEVI void mma16n8k16(float& c0, float& c1, float& c2, float& c3,
                     uint32_t a0, uint32_t a1, uint32_t a2, uint32_t a3,
                     uint32_t b0, uint32_t b1) {
    asm volatile(
        "mma.sync.aligned.m16n8k16.row.col.f32.f16.f16.f32 "
        "{%0,%1,%2,%3}, {%4,%5,%6,%7}, {%8,%9}, {%0,%1,%2,%3};"
        : "+f"(c0), "+f"(c1), "+f"(c2), "+f"(c3)
        : "r"(a0), "r"(a1), "r"(a2), "r"(a3), "r"(b0), "r"(b1));
}
DEVI void cp_async16(uint32_t dst, const void* src) {
    asm volatile("cp.async.cg.shared.global [%0], [%1], 16;" :: "r"(dst), "l"(src) : "memory");
}
DEVI void cp_commit()  { asm volatile("cp.async.commit_group;" ::: "memory"); }
DEVI void cp_wait0()   { asm volatile("cp.async.wait_group 0;" ::: "memory"); }

// Owned prefetch into the single stage buffer (linear layout, same mapping as convert)
DEVI void prefetch(uint32_t stage_addr, const float* __restrict__ gb, int tid) {
#pragma unroll 1
    for (int p = tid; p < NPAIRS; p += NTHREADS) {
        int b   = p / 400;
        int r   = p - b * 400;
        int f2  = r >> 4;
        int seg = r & 15;
        int off = b * FE + (2 * f2) * E_DIM + seg * 4;
        cp_async16(stage_addr + (uint32_t)off * 4u,           gb + off);
        cp_async16(stage_addr + (uint32_t)(off + E_DIM) * 4u, gb + off + E_DIM);
    }
}

// Owned convert: thread converts exactly the pairs it prefetched.
DEVI void convert(uint32_t* __restrict__ x16dst, const float* __restrict__ st, int tid) {
#pragma unroll 1
    for (int p = tid; p < NPAIRS; p += NTHREADS) {
        int b   = p / 400;
        int r   = p - b * 400;
        int f2  = r >> 4;
        int seg = r & 15;
        const float* p0 = st + b * FE + (2 * f2) * E_DIM + seg * 4;
        float4 lo = *reinterpret_cast<const float4*>(p0);
        float4 hi = *reinterpret_cast<const float4*>(p0 + E_DIM);
        uint4 q;
        q.x = pack_h2(lo.x, hi.x);
        q.y = pack_h2(lo.y, hi.y);
        q.z = pack_h2(lo.z, hi.z);
        q.w = pack_h2(lo.w, hi.w);
        *reinterpret_cast<uint4*>(x16dst + b * X16_BATCH + f2 * X16_STR + seg * 4) = q;
    }
}

// ---------------------------------------------------------------------------
__global__ void __launch_bounds__(NTHREADS, 3)
InnerProduct_65429531787441_kernel(const float* __restrict__ X,
                                   const float* __restrict__ Th,
                                   float* __restrict__ out) {
    extern __shared__ uint32_t smu[];
    uint32_t* afr   = smu;                           // A-frag table (f16x2)
    uint32_t* x16   = smu + X16_OFF;                 // fp16 B tile (2 buffers)
    float*    stage = reinterpret_cast<float*>(smu + ST_OFF);
    const uint32_t stage_addr = smem_u32(stage);

    const int tid  = threadIdx.x;
    const int lane = tid & 31;
    const int w    = tid >> 5;
    const int b_l  = w >> 2;        // batch slot 0..1
    const int mq   = w & 3;         // d quarter
    const int lg   = lane >> 2;     // 0..7
    const int lq   = lane & 3;      // 0..3

    const int gi0 = blockIdx.x;

    // Prologue: prefetch group gi0 into the stage
    prefetch(stage_addr, X + (size_t)gi0 * GRP_G, tid);
    cp_commit();

    // Build A-frag table (Theta fp16 pairs, m16n8k16 frag order, zero-pad f>=50)
    for (int i = tid; i < AFRAG_U32; i += NTHREADS) {
        int j   = i & 3;
        int ln  = (i >> 2) & 31;
        int mi  = (i >> 7) & 1;
        int s   = (i >> 8) & 3;
        int mq_ = i >> 10;
        int row = mq_ * 32 + mi * 16 + (j & 1) * 8 + (ln >> 2);
        int k0  = 16 * s + 2 * (ln & 3) + (j >> 1) * 8;
        float v0 = (k0     < F_DIM) ? Th[row * F_DIM + k0]     : 0.f;
        float v1 = (k0 + 1 < F_DIM) ? Th[row * F_DIM + k0 + 1] : 0.f;
        afr[i] = pack_h2(v0, v1);
    }

    cp_wait0();                        // group gi0 landed (own chunks visible)
    convert(x16, stage, tid);          // group gi0 -> x16[0]
    if (gi0 + GRID < NGI)
        prefetch(stage_addr, X + (size_t)(gi0 + GRID) * GRP_G, tid);  // overwrite own chunks
    cp_commit();
    __syncthreads();                   // publish afr + x16[0]

    const uint4* afr4 = reinterpret_cast<const uint4*>(afr);

    int it = 0;
    for (int gi = gi0; gi < NGI; gi += GRID, ++it) {
        const int buf = it & 1;

        // 1) Wait for group gi+GRID in the stage; convert it into x16[buf^1].
        //    (x16[buf^1] was last read in iter it-1; closed by that iter's barrier.)
        cp_wait0();
        if (gi + GRID < NGI)
            convert(x16 + (buf ^ 1) * X16_BUF, stage, tid);

        // 2) Refill stage with group gi+2*GRID (own-chunk overwrite is safe).
        if (gi + 2 * GRID < NGI)
            prefetch(stage_addr, X + (size_t)(gi + 2 * GRID) * GRP_G, tid);
        cp_commit();

        // 3) MMA on current group from x16[buf]
        const uint32_t* xb = x16 + buf * X16_BUF + b_l * X16_BATCH;

        float acc[2][8][4];
#pragma unroll
        for (int mi = 0; mi < 2; mi++)
#pragma unroll
            for (int ni = 0; ni < 8; ni++)
#pragma unroll
                for (int j = 0; j < 4; j++) acc[mi][ni][j] = 0.f;

#pragma unroll
        for (int s = 0; s < 4; s++) {
            const uint4 A0 = afr4[((mq * 4 + s) * 2 + 0) * 32 + lane];
            const uint4 A1 = afr4[((mq * 4 + s) * 2 + 1) * 32 + lane];
            const int f2a = 8 * s + lq;
#pragma unroll
            for (int ni = 0; ni < 8; ni++) {
                const int e = ni * 8 + lg;
                uint32_t b0, b1;
                if (s < 3) {
                    b0 = xb[f2a * X16_STR + e];
                    b1 = xb[(f2a + 4) * X16_STR + e];
                } else {
                    // s == 3: rows 24 (f 48,49) real only for lq==0; rest zero
                    b0 = (lq == 0) ? xb[24 * X16_STR + e] : 0u;
                    b1 = 0u;
                }
                mma16n8k16(acc[0][ni][0], acc[0][ni][1], acc[0][ni][2], acc[0][ni][3],
                           A0.x, A0.y, A0.z, A0.w, b0, b1);
                mma16n8k16(acc[1][ni][0], acc[1][ni][1], acc[1][ni][2], acc[1][ni][3],
                           A1.x, A1.y, A1.z, A1.w, b0, b1);
            }
        }

        // 4) Epilogue: sum of squares over this warp's full e-range, shfl, store
        float* orow = out + (size_t)(gi * BPI + b_l) * D_DIM;
#pragma unroll
        for (int mi = 0; mi < 2; mi++) {
            float a = 0.f, b = 0.f;
#pragma unroll
            for (int ni = 0; ni < 8; ni++) {
                a = fmaf(acc[mi][ni][0], acc[mi][ni][0], a);
                a = fmaf(acc[mi][ni][1], acc[mi][ni][1], a);
                b = fmaf(acc[mi][ni][2], acc[mi][ni][2], b);
                b = fmaf(acc[mi][ni][3], acc[mi][ni][3], b);
            }
            a += __shfl_xor_sync(0xffffffffu, a, 1);
            a += __shfl_xor_sync(0xffffffffu, a, 2);
            b += __shfl_xor_sync(0xffffffffu, b, 1);
            b += __shfl_xor_sync(0xffffffffu, b, 2);
            if (lq == 0) {
                const int d = mq * 32 + mi * 16 + lg;
                orow[d]     = a;
                orow[d + 8] = b;
            }
        }

        __syncthreads();  // publish x16[buf^1]; close x16[buf] reads for next iter
    }
}

extern "C" void kernel_launch(void* const* d_in, const int* in_sizes, int n_in,
                              void* d_out, int out_size) {
    (void)in_sizes; (void)n_in; (void)out_size;
    const float* X  = (const float*)d_in[0];
    const float* Th = (const float*)d_in[1];
    float* out = (float*)d_out;
    cudaFuncSetAttribute(InnerProduct_65429531787441_kernel,
                         cudaFuncAttributeMaxDynamicSharedMemorySize, SMEM_BYTES);
    InnerProduct_65429531787441_kernel<<<GRID, NTHREADS, SMEM_BYTES>>>(X, Th, out);
}